// round 10
// baseline (speedup 1.0000x reference)
#include <cuda_runtime.h>
#include <math_constants.h>

#define NPIX_MAX (32 * 128 * 2048)
#define TB   256
#define GRID (148 * 8)   // 1184

__device__ float        g_gray[NPIX_MAX];
__device__ float        g_pmin[GRID];
__device__ float        g_pmax[GRID];
__device__ unsigned int g_hist[256];   // zeroed by K1 block 0 each replay (and statically at load)

__device__ __forceinline__ float gray_of(float r, float g, float b) {
    return fmaf(0.1140f, b, fmaf(0.5870f, g, __fmul_rn(0.2989f, r)));
}

// block-wide min/max reduction of the partial arrays -> (vmin, vmax)
__device__ __forceinline__ void reduce_partials(float* rmin, float* rmax,
                                                float& vmin, float& vmax) {
    const int t = threadIdx.x;
    float lmin = CUDART_INF_F, lmax = -CUDART_INF_F;
    for (int i = t; i < GRID; i += TB) {
        lmin = fminf(lmin, g_pmin[i]);
        lmax = fmaxf(lmax, g_pmax[i]);
    }
    rmin[t] = lmin; rmax[t] = lmax;
    __syncthreads();
    for (int s = 128; s; s >>= 1) {
        if (t < s) {
            rmin[t] = fminf(rmin[t], rmin[t + s]);
            rmax[t] = fmaxf(rmax[t], rmax[t + s]);
        }
        __syncthreads();
    }
    vmin = rmin[0];
    vmax = rmax[0];
    __syncthreads();
}

// ---------------- K1: gray + per-block min/max (smem-staged) --------------
__global__ void gray_minmax_kernel(const float* __restrict__ in, int npix) {
    __shared__ float4 stage[TB * 3];            // 12 KB
    const int ngroups = npix >> 2;
    const int nf4     = ngroups * 3;
    const int ntiles  = (ngroups + TB - 1) / TB;
    const float4* __restrict__ in4 = (const float4*)in;
    float4* __restrict__ gr4 = (float4*)g_gray;
    const int t = threadIdx.x;

    // reset histogram for this replay (read only in K3, accumulated in K2)
    if (blockIdx.x == 0 && t < 256) g_hist[t] = 0u;

    float lmin = CUDART_INF_F, lmax = -CUDART_INF_F;

    for (int tile = blockIdx.x; tile < ntiles; tile += gridDim.x) {
        const int gbase = tile * TB;
        const int fbase = gbase * 3;
        #pragma unroll
        for (int j = 0; j < 3; j++) {
            int idx = t + j * TB;
            if (fbase + idx < nf4) stage[idx] = in4[fbase + idx];
        }
        __syncthreads();
        const int g = gbase + t;
        if (g < ngroups) {
            float4 a = stage[3 * t + 0];
            float4 b = stage[3 * t + 1];
            float4 c = stage[3 * t + 2];
            float g0 = gray_of(a.x, a.y, a.z);
            float g1 = gray_of(a.w, b.x, b.y);
            float g2 = gray_of(b.z, b.w, c.x);
            float g3 = gray_of(c.y, c.z, c.w);
            gr4[g] = make_float4(g0, g1, g2, g3);
            lmin = fminf(lmin, fminf(fminf(g0, g1), fminf(g2, g3)));
            lmax = fmaxf(lmax, fmaxf(fmaxf(g0, g1), fmaxf(g2, g3)));
        }
        __syncthreads();
    }
    const int stride = gridDim.x * blockDim.x;
    for (int p = (ngroups << 2) + blockIdx.x * blockDim.x + t; p < npix; p += stride) {
        float gg = gray_of(in[3 * p], in[3 * p + 1], in[3 * p + 2]);
        g_gray[p] = gg;
        lmin = fminf(lmin, gg);
        lmax = fmaxf(lmax, gg);
    }

    for (int o = 16; o; o >>= 1) {
        lmin = fminf(lmin, __shfl_xor_sync(0xFFFFFFFFu, lmin, o));
        lmax = fmaxf(lmax, __shfl_xor_sync(0xFFFFFFFFu, lmax, o));
    }
    __shared__ float smin[8], smax[8];
    int wid = t >> 5, lid = t & 31;
    if (lid == 0) { smin[wid] = lmin; smax[wid] = lmax; }
    __syncthreads();
    if (t == 0) {
        float bmin = smin[0], bmax = smax[0];
        #pragma unroll
        for (int i = 1; i < (TB >> 5); i++) {
            bmin = fminf(bmin, smin[i]);
            bmax = fmaxf(bmax, smax[i]);
        }
        g_pmin[blockIdx.x] = bmin;     // plain stores: no init required
        g_pmax[blockIdx.x] = bmax;
    }
}

// ---------------- K2: reduce partials + 256-bin histogram ------------------
__global__ void hist_kernel(int npix) {
    __shared__ unsigned int sh[256 * 8];       // 8 KB
    __shared__ float rmin[256], rmax[256];     // 2 KB

    float vmin, vmax;
    reduce_partials(rmin, rmax, vmin, vmax);

    for (int i = threadIdx.x; i < 256 * 8; i += blockDim.x) sh[i] = 0u;
    __syncthreads();

    const float scale = 256.0f / (vmax - vmin);
    unsigned int* my = sh + ((threadIdx.x >> 5) & 7) * 256;
    const int ngroups = npix >> 2;
    const int stride  = gridDim.x * blockDim.x;
    const float4* __restrict__ gr4 = (const float4*)g_gray;

    for (int g = blockIdx.x * blockDim.x + threadIdx.x; g < ngroups; g += stride) {
        float4 v = __ldcg(&gr4[g]);
        int b0 = min(255, max(0, (int)((v.x - vmin) * scale)));
        int b1 = min(255, max(0, (int)((v.y - vmin) * scale)));
        int b2 = min(255, max(0, (int)((v.z - vmin) * scale)));
        int b3 = min(255, max(0, (int)((v.w - vmin) * scale)));
        atomicAdd(&my[b0], 1u);
        atomicAdd(&my[b1], 1u);
        atomicAdd(&my[b2], 1u);
        atomicAdd(&my[b3], 1u);
    }
    for (int p = (ngroups << 2) + blockIdx.x * blockDim.x + threadIdx.x; p < npix; p += stride) {
        int b = min(255, max(0, (int)((__ldcg(&g_gray[p]) - vmin) * scale)));
        atomicAdd(&my[b], 1u);
    }
    __syncthreads();
    for (int i = threadIdx.x; i < 256; i += blockDim.x) {
        unsigned int s = 0;
        #pragma unroll
        for (int r = 0; r < 8; r++) s += sh[r * 256 + i];
        if (s) atomicAdd(&g_hist[i], s);
    }
}

// -------- K3: partials + Otsu prologue + direct binarize (4x ILP) ----------
__global__ void binarize_kernel(float* __restrict__ out, int npix) {
    __shared__ struct {
        float c[256], w1[256], s1[256], w2[256], s2[256], bv[256];
        int bi[256];
    } sh;
    __shared__ float rmin[256], rmax[256];
    __shared__ float s_thresh;
    const int t = threadIdx.x;

    // ---- Otsu prologue (every block) ----
    {
        float vmin, vmax;
        reduce_partials(rmin, rmax, vmin, vmax);
        const float step = __fmul_rn(__fadd_rn(vmax, -vmin), 1.0f / 256.0f);

        float e0 = __fadd_rn(vmin, __fmul_rn(step, (float)t));
        float e1 = (t == 255) ? vmax : __fadd_rn(vmin, __fmul_rn(step, (float)(t + 1)));
        float ct = __fmul_rn(__fadd_rn(e0, e1), 0.5f);
        sh.c[t] = ct;

        float hv = (float)g_hist[t];
        float hc = __fmul_rn(hv, ct);
        sh.w1[t] = hv; sh.s1[t] = hc;
        sh.w2[t] = hv; sh.s2[t] = hc;
        __syncthreads();

        #pragma unroll
        for (int s = 1; s < 256; s <<= 1) {
            float aw1 = (t >= s)      ? sh.w1[t - s] : 0.0f;
            float as1 = (t >= s)      ? sh.s1[t - s] : 0.0f;
            float aw2 = (t + s < 256) ? sh.w2[t + s] : 0.0f;
            float as2 = (t + s < 256) ? sh.s2[t + s] : 0.0f;
            __syncthreads();
            sh.w1[t] = __fadd_rn(sh.w1[t], aw1);
            sh.s1[t] = __fadd_rn(sh.s1[t], as1);
            sh.w2[t] = __fadd_rn(sh.w2[t], aw2);
            sh.s2[t] = __fadd_rn(sh.s2[t], as2);
            __syncthreads();
        }

        float v = -CUDART_INF_F;
        if (t < 255) {
            float m1 = sh.s1[t] / fmaxf(sh.w1[t], 1.0f);
            float m2 = sh.s2[t + 1] / fmaxf(sh.w2[t + 1], 1.0f);
            float d = __fadd_rn(m1, -m2);
            v = __fmul_rn(__fmul_rn(sh.w1[t], sh.w2[t + 1]), __fmul_rn(d, d));
        }
        sh.bv[t] = v; sh.bi[t] = t;
        __syncthreads();
        for (int s = 128; s; s >>= 1) {
            if (t < s) {
                float ov = sh.bv[t + s]; int oi = sh.bi[t + s];
                if (ov > sh.bv[t] || (ov == sh.bv[t] && oi < sh.bi[t])) {
                    sh.bv[t] = ov; sh.bi[t] = oi;
                }
            }
            __syncthreads();
        }
        if (t == 0) s_thresh = sh.c[sh.bi[0]];
        __syncthreads();
    }

    // ---- direct streaming binarize: 4 out-float4 per iteration ----
    const float thr = s_thresh;
    const int nout4 = (npix * 3) >> 2;
    const int stride = gridDim.x * blockDim.x;
    const float* __restrict__ gray = g_gray;
    float4* __restrict__ o4 = (float4*)out;

    int f = blockIdx.x * blockDim.x + t;
    for (; f + 3 * stride < nout4; f += 4 * stride) {
        #pragma unroll
        for (int u = 0; u < 4; u++) {
            const int fu = f + u * stride;
            const int e0 = 4 * fu;
            const int p0 = e0 / 3;
            const int r  = e0 - 3 * p0;
            float ga = __ldg(&gray[p0]);
            float gb = __ldg(&gray[p0 + 1]);
            float ba = (ga > thr) ? 1.0f : 0.0f;
            float bb = (gb > thr) ? 1.0f : 0.0f;
            float4 v;
            v.x = ba;
            v.y = (r < 2) ? ba : bb;
            v.z = (r < 1) ? ba : bb;
            v.w = bb;
            o4[fu] = v;
        }
    }
    for (; f < nout4; f += stride) {
        const int e0 = 4 * f;
        const int p0 = e0 / 3;
        const int r  = e0 - 3 * p0;
        float ga = __ldg(&gray[p0]);
        float gb = __ldg(&gray[p0 + 1]);
        float ba = (ga > thr) ? 1.0f : 0.0f;
        float bb = (gb > thr) ? 1.0f : 0.0f;
        float4 v;
        v.x = ba;
        v.y = (r < 2) ? ba : bb;
        v.z = (r < 1) ? ba : bb;
        v.w = bb;
        o4[f] = v;
    }
    for (int e = (nout4 << 2) + blockIdx.x * blockDim.x + t; e < npix * 3; e += stride) {
        float g = __ldg(&gray[e / 3]);
        out[e] = (g > thr) ? 1.0f : 0.0f;
    }
}

// ---------------- launch ---------------------------------------------------
extern "C" void kernel_launch(void* const* d_in, const int* in_sizes, int n_in,
                              void* d_out, int out_size) {
    const float* in = (const float*)d_in[0];
    float* out = (float*)d_out;
    int npix = in_sizes[0] / 3;

    gray_minmax_kernel<<<GRID, TB>>>(in, npix);
    hist_kernel<<<GRID, TB>>>(npix);
    binarize_kernel<<<GRID, TB>>>(out, npix);
}

// round 12
// speedup vs baseline: 1.0722x; 1.0722x over previous
#include <cuda_runtime.h>
#include <math_constants.h>

#define NPIX_MAX (32 * 128 * 2048)
#define TB   256
#define GRID (148 * 8)   // 1184

__device__ float        g_gray[NPIX_MAX];
__device__ unsigned int g_min_bits;
__device__ unsigned int g_max_bits;
__device__ unsigned int g_hist[256];

__device__ __forceinline__ unsigned int f_enc(float f) {
    unsigned int u = __float_as_uint(f);
    return (u & 0x80000000u) ? ~u : (u | 0x80000000u);
}
__device__ __forceinline__ float f_dec(unsigned int e) {
    unsigned int u = (e & 0x80000000u) ? (e & 0x7FFFFFFFu) : ~e;
    return __uint_as_float(u);
}
__device__ __forceinline__ float gray_of(float r, float g, float b) {
    return fmaf(0.1140f, b, fmaf(0.5870f, g, __fmul_rn(0.2989f, r)));
}

// ---------------- K0: reset state (inside graph, every replay) -------------
__global__ void init_kernel() {
    int t = threadIdx.x;
    if (t < 256) g_hist[t] = 0u;
    if (t == 0) {
        g_min_bits = 0xFFFFFFFFu;
        g_max_bits = 0x00000000u;
    }
}

// ---------------- K1: gray + min/max (smem-staged coalesced loads) ---------
__global__ void gray_minmax_kernel(const float* __restrict__ in, int npix) {
    __shared__ float4 stage[TB * 3];            // 12 KB
    const int ngroups = npix >> 2;
    const int nf4     = ngroups * 3;
    const int ntiles  = (ngroups + TB - 1) / TB;
    const float4* __restrict__ in4 = (const float4*)in;
    float4* __restrict__ gr4 = (float4*)g_gray;
    const int t = threadIdx.x;

    float lmin = CUDART_INF_F, lmax = -CUDART_INF_F;

    for (int tile = blockIdx.x; tile < ntiles; tile += gridDim.x) {
        const int gbase = tile * TB;
        const int fbase = gbase * 3;
        #pragma unroll
        for (int j = 0; j < 3; j++) {
            int idx = t + j * TB;
            if (fbase + idx < nf4) stage[idx] = in4[fbase + idx];
        }
        __syncthreads();
        const int g = gbase + t;
        if (g < ngroups) {
            float4 a = stage[3 * t + 0];
            float4 b = stage[3 * t + 1];
            float4 c = stage[3 * t + 2];
            float g0 = gray_of(a.x, a.y, a.z);
            float g1 = gray_of(a.w, b.x, b.y);
            float g2 = gray_of(b.z, b.w, c.x);
            float g3 = gray_of(c.y, c.z, c.w);
            gr4[g] = make_float4(g0, g1, g2, g3);
            lmin = fminf(lmin, fminf(fminf(g0, g1), fminf(g2, g3)));
            lmax = fmaxf(lmax, fmaxf(fmaxf(g0, g1), fmaxf(g2, g3)));
        }
        __syncthreads();
    }
    const int stride = gridDim.x * blockDim.x;
    for (int p = (ngroups << 2) + blockIdx.x * blockDim.x + t; p < npix; p += stride) {
        float gg = gray_of(in[3 * p], in[3 * p + 1], in[3 * p + 2]);
        g_gray[p] = gg;
        lmin = fminf(lmin, gg);
        lmax = fmaxf(lmax, gg);
    }

    for (int o = 16; o; o >>= 1) {
        lmin = fminf(lmin, __shfl_xor_sync(0xFFFFFFFFu, lmin, o));
        lmax = fmaxf(lmax, __shfl_xor_sync(0xFFFFFFFFu, lmax, o));
    }
    __shared__ float smin[8], smax[8];
    int wid = t >> 5, lid = t & 31;
    if (lid == 0) { smin[wid] = lmin; smax[wid] = lmax; }
    __syncthreads();
    if (t == 0) {
        float bmin = smin[0], bmax = smax[0];
        #pragma unroll
        for (int i = 1; i < (TB >> 5); i++) {
            bmin = fminf(bmin, smin[i]);
            bmax = fmaxf(bmax, smax[i]);
        }
        atomicMin(&g_min_bits, f_enc(bmin));
        atomicMax(&g_max_bits, f_enc(bmax));
    }
}

// ---------------- K2: 256-bin histogram ------------------------------------
__global__ void hist_kernel(int npix) {
    __shared__ unsigned int sh[256 * 8];
    for (int i = threadIdx.x; i < 256 * 8; i += blockDim.x) sh[i] = 0u;
    __syncthreads();

    const float vmin = f_dec(g_min_bits);
    const float vmax = f_dec(g_max_bits);
    const float scale = 256.0f / (vmax - vmin);

    unsigned int* my = sh + ((threadIdx.x >> 5) & 7) * 256;
    const int ngroups = npix >> 2;
    const int stride  = gridDim.x * blockDim.x;
    const float4* __restrict__ gr4 = (const float4*)g_gray;

    for (int g = blockIdx.x * blockDim.x + threadIdx.x; g < ngroups; g += stride) {
        float4 v = __ldcg(&gr4[g]);
        int b0 = min(255, max(0, (int)((v.x - vmin) * scale)));
        int b1 = min(255, max(0, (int)((v.y - vmin) * scale)));
        int b2 = min(255, max(0, (int)((v.z - vmin) * scale)));
        int b3 = min(255, max(0, (int)((v.w - vmin) * scale)));
        atomicAdd(&my[b0], 1u);
        atomicAdd(&my[b1], 1u);
        atomicAdd(&my[b2], 1u);
        atomicAdd(&my[b3], 1u);
    }
    for (int p = (ngroups << 2) + blockIdx.x * blockDim.x + threadIdx.x; p < npix; p += stride) {
        int b = min(255, max(0, (int)((__ldcg(&g_gray[p]) - vmin) * scale)));
        atomicAdd(&my[b], 1u);
    }
    __syncthreads();
    for (int i = threadIdx.x; i < 256; i += blockDim.x) {
        unsigned int s = 0;
        #pragma unroll
        for (int r = 0; r < 8; r++) s += sh[r * 256 + i];
        if (s) atomicAdd(&g_hist[i], s);
    }
}

// -------- K3: Otsu prologue + direct binarize (4x ILP) ---------------------
__global__ void binarize_kernel(float* __restrict__ out, int npix) {
    __shared__ struct {
        float c[256], w1[256], s1[256], w2[256], s2[256], bv[256];
        int bi[256];
    } sh;
    __shared__ float s_thresh;
    const int t = threadIdx.x;

    // ---- Otsu prologue: every block computes threshold from g_hist ----
    {
        const float vmin = f_dec(g_min_bits);
        const float vmax = f_dec(g_max_bits);
        const float step = __fmul_rn(__fadd_rn(vmax, -vmin), 1.0f / 256.0f);

        float e0 = __fadd_rn(vmin, __fmul_rn(step, (float)t));
        float e1 = (t == 255) ? vmax : __fadd_rn(vmin, __fmul_rn(step, (float)(t + 1)));
        float ct = __fmul_rn(__fadd_rn(e0, e1), 0.5f);
        sh.c[t] = ct;

        float hv = (float)g_hist[t];
        float hc = __fmul_rn(hv, ct);
        sh.w1[t] = hv; sh.s1[t] = hc;
        sh.w2[t] = hv; sh.s2[t] = hc;
        __syncthreads();

        #pragma unroll
        for (int s = 1; s < 256; s <<= 1) {
            float aw1 = (t >= s)      ? sh.w1[t - s] : 0.0f;
            float as1 = (t >= s)      ? sh.s1[t - s] : 0.0f;
            float aw2 = (t + s < 256) ? sh.w2[t + s] : 0.0f;
            float as2 = (t + s < 256) ? sh.s2[t + s] : 0.0f;
            __syncthreads();
            sh.w1[t] = __fadd_rn(sh.w1[t], aw1);
            sh.s1[t] = __fadd_rn(sh.s1[t], as1);
            sh.w2[t] = __fadd_rn(sh.w2[t], aw2);
            sh.s2[t] = __fadd_rn(sh.s2[t], as2);
            __syncthreads();
        }

        float v = -CUDART_INF_F;
        if (t < 255) {
            float m1 = sh.s1[t] / fmaxf(sh.w1[t], 1.0f);
            float m2 = sh.s2[t + 1] / fmaxf(sh.w2[t + 1], 1.0f);
            float d = __fadd_rn(m1, -m2);
            v = __fmul_rn(__fmul_rn(sh.w1[t], sh.w2[t + 1]), __fmul_rn(d, d));
        }
        sh.bv[t] = v; sh.bi[t] = t;
        __syncthreads();
        for (int s = 128; s; s >>= 1) {
            if (t < s) {
                float ov = sh.bv[t + s]; int oi = sh.bi[t + s];
                if (ov > sh.bv[t] || (ov == sh.bv[t] && oi < sh.bi[t])) {
                    sh.bv[t] = ov; sh.bi[t] = oi;
                }
            }
            __syncthreads();
        }
        if (t == 0) s_thresh = sh.c[sh.bi[0]];
        __syncthreads();
    }

    // ---- direct streaming binarize: 4 out-float4 per iteration ----
    const float thr = s_thresh;
    const int nout4 = (npix * 3) >> 2;
    const int stride = gridDim.x * blockDim.x;
    const float* __restrict__ gray = g_gray;
    float4* __restrict__ o4 = (float4*)out;

    int f = blockIdx.x * blockDim.x + t;
    for (; f + 3 * stride < nout4; f += 4 * stride) {
        #pragma unroll
        for (int u = 0; u < 4; u++) {
            const int fu = f + u * stride;
            const int e0 = 4 * fu;
            const int p0 = e0 / 3;
            const int r  = e0 - 3 * p0;
            float ga = __ldg(&gray[p0]);
            float gb = __ldg(&gray[p0 + 1]);
            float ba = (ga > thr) ? 1.0f : 0.0f;
            float bb = (gb > thr) ? 1.0f : 0.0f;
            float4 v;
            v.x = ba;
            v.y = (r < 2) ? ba : bb;
            v.z = (r < 1) ? ba : bb;
            v.w = bb;
            o4[fu] = v;
        }
    }
    for (; f < nout4; f += stride) {
        const int e0 = 4 * f;
        const int p0 = e0 / 3;
        const int r  = e0 - 3 * p0;
        float ga = __ldg(&gray[p0]);
        float gb = __ldg(&gray[p0 + 1]);
        float ba = (ga > thr) ? 1.0f : 0.0f;
        float bb = (gb > thr) ? 1.0f : 0.0f;
        float4 v;
        v.x = ba;
        v.y = (r < 2) ? ba : bb;
        v.z = (r < 1) ? ba : bb;
        v.w = bb;
        o4[f] = v;
    }
    for (int e = (nout4 << 2) + blockIdx.x * blockDim.x + t; e < npix * 3; e += stride) {
        float g = __ldg(&gray[e / 3]);
        out[e] = (g > thr) ? 1.0f : 0.0f;
    }
}

// ---------------- launch ---------------------------------------------------
extern "C" void kernel_launch(void* const* d_in, const int* in_sizes, int n_in,
                              void* d_out, int out_size) {
    const float* in = (const float*)d_in[0];
    float* out = (float*)d_out;
    int npix = in_sizes[0] / 3;

    init_kernel<<<1, 256>>>();
    gray_minmax_kernel<<<GRID, TB>>>(in, npix);
    hist_kernel<<<GRID, TB>>>(npix);
    binarize_kernel<<<GRID, TB>>>(out, npix);
}

// round 13
// speedup vs baseline: 1.0762x; 1.0038x over previous
#include <cuda_runtime.h>
#include <math_constants.h>

#define NPIX_MAX (32 * 128 * 2048)
#define TB   256
#define GRID (148 * 8)   // 1184

__device__ float        g_gray[NPIX_MAX];
__device__ unsigned int g_min_bits = 0xFFFFFFFFu;   // reset by hist last-block each run
__device__ unsigned int g_max_bits = 0x00000000u;
__device__ unsigned int g_hist[256];                // zero-init; reset by hist last-block
__device__ unsigned int g_done = 0u;                // last-block counter; self-resetting
__device__ float        g_thresh;                   // written each run before binarize reads

__device__ __forceinline__ unsigned int f_enc(float f) {
    unsigned int u = __float_as_uint(f);
    return (u & 0x80000000u) ? ~u : (u | 0x80000000u);
}
__device__ __forceinline__ float f_dec(unsigned int e) {
    unsigned int u = (e & 0x80000000u) ? (e & 0x7FFFFFFFu) : ~e;
    return __uint_as_float(u);
}
__device__ __forceinline__ float gray_of(float r, float g, float b) {
    return fmaf(0.1140f, b, fmaf(0.5870f, g, __fmul_rn(0.2989f, r)));
}

// ---------------- K1: gray + min/max (smem-staged coalesced loads) ---------
__global__ void gray_minmax_kernel(const float* __restrict__ in, int npix) {
    __shared__ float4 stage[TB * 3];            // 12 KB
    const int ngroups = npix >> 2;
    const int nf4     = ngroups * 3;
    const int ntiles  = (ngroups + TB - 1) / TB;
    const float4* __restrict__ in4 = (const float4*)in;
    float4* __restrict__ gr4 = (float4*)g_gray;
    const int t = threadIdx.x;

    float lmin = CUDART_INF_F, lmax = -CUDART_INF_F;

    for (int tile = blockIdx.x; tile < ntiles; tile += gridDim.x) {
        const int gbase = tile * TB;
        const int fbase = gbase * 3;
        #pragma unroll
        for (int j = 0; j < 3; j++) {
            int idx = t + j * TB;
            if (fbase + idx < nf4) stage[idx] = in4[fbase + idx];
        }
        __syncthreads();
        const int g = gbase + t;
        if (g < ngroups) {
            float4 a = stage[3 * t + 0];
            float4 b = stage[3 * t + 1];
            float4 c = stage[3 * t + 2];
            float g0 = gray_of(a.x, a.y, a.z);
            float g1 = gray_of(a.w, b.x, b.y);
            float g2 = gray_of(b.z, b.w, c.x);
            float g3 = gray_of(c.y, c.z, c.w);
            gr4[g] = make_float4(g0, g1, g2, g3);
            lmin = fminf(lmin, fminf(fminf(g0, g1), fminf(g2, g3)));
            lmax = fmaxf(lmax, fmaxf(fmaxf(g0, g1), fmaxf(g2, g3)));
        }
        __syncthreads();
    }
    const int stride = gridDim.x * blockDim.x;
    for (int p = (ngroups << 2) + blockIdx.x * blockDim.x + t; p < npix; p += stride) {
        float gg = gray_of(in[3 * p], in[3 * p + 1], in[3 * p + 2]);
        g_gray[p] = gg;
        lmin = fminf(lmin, gg);
        lmax = fmaxf(lmax, gg);
    }

    for (int o = 16; o; o >>= 1) {
        lmin = fminf(lmin, __shfl_xor_sync(0xFFFFFFFFu, lmin, o));
        lmax = fmaxf(lmax, __shfl_xor_sync(0xFFFFFFFFu, lmax, o));
    }
    __shared__ float smin[8], smax[8];
    int wid = t >> 5, lid = t & 31;
    if (lid == 0) { smin[wid] = lmin; smax[wid] = lmax; }
    __syncthreads();
    if (t == 0) {
        float bmin = smin[0], bmax = smax[0];
        #pragma unroll
        for (int i = 1; i < (TB >> 5); i++) {
            bmin = fminf(bmin, smin[i]);
            bmax = fmaxf(bmax, smax[i]);
        }
        atomicMin(&g_min_bits, f_enc(bmin));
        atomicMax(&g_max_bits, f_enc(bmax));
    }
}

// ------- K2: histogram + last-block Otsu + state reset ---------------------
struct HistShared {
    union {
        unsigned int hist[256 * 8];   // 8 KB (accumulation)
        struct {
            float c[256], w1[256], s1[256], w2[256], s2[256], bv[256];
            int bi[256];
        } o;                           // 7 KB (last-block otsu)
    };
};

__global__ void hist_kernel(int npix) {
    __shared__ HistShared sh;
    __shared__ unsigned int s_last;
    const int t = threadIdx.x;

    for (int i = t; i < 256 * 8; i += TB) sh.hist[i] = 0u;
    __syncthreads();

    const float vmin = f_dec(g_min_bits);
    const float vmax = f_dec(g_max_bits);
    const float scale = 256.0f / (vmax - vmin);

    unsigned int* my = sh.hist + ((t >> 5) & 7) * 256;
    const int ngroups = npix >> 2;
    const int stride  = gridDim.x * blockDim.x;
    const float4* __restrict__ gr4 = (const float4*)g_gray;

    for (int g = blockIdx.x * TB + t; g < ngroups; g += stride) {
        float4 v = __ldcg(&gr4[g]);
        int b0 = min(255, max(0, (int)((v.x - vmin) * scale)));
        int b1 = min(255, max(0, (int)((v.y - vmin) * scale)));
        int b2 = min(255, max(0, (int)((v.z - vmin) * scale)));
        int b3 = min(255, max(0, (int)((v.w - vmin) * scale)));
        atomicAdd(&my[b0], 1u);
        atomicAdd(&my[b1], 1u);
        atomicAdd(&my[b2], 1u);
        atomicAdd(&my[b3], 1u);
    }
    for (int p = (ngroups << 2) + blockIdx.x * TB + t; p < npix; p += stride) {
        int b = min(255, max(0, (int)((__ldcg(&g_gray[p]) - vmin) * scale)));
        atomicAdd(&my[b], 1u);
    }
    __syncthreads();
    for (int i = t; i < 256; i += TB) {
        unsigned int s = 0;
        #pragma unroll
        for (int r = 0; r < 8; r++) s += sh.hist[r * 256 + i];
        if (s) atomicAdd(&g_hist[i], s);
    }

    // ---- last-block-done: compute Otsu threshold + reset state ----
    __threadfence();
    if (t == 0) s_last = (atomicAdd(&g_done, 1u) == (unsigned)gridDim.x - 1u) ? 1u : 0u;
    __syncthreads();
    if (s_last) {
        __threadfence();   // acquire: see all blocks' g_hist atomics

        const float step = __fmul_rn(__fadd_rn(vmax, -vmin), 1.0f / 256.0f);
        float e0 = __fadd_rn(vmin, __fmul_rn(step, (float)t));
        float e1 = (t == 255) ? vmax : __fadd_rn(vmin, __fmul_rn(step, (float)(t + 1)));
        float ct = __fmul_rn(__fadd_rn(e0, e1), 0.5f);

        float hv = (float)g_hist[t];
        // reset for next replay (value already captured)
        g_hist[t] = 0u;
        if (t == 0) {
            g_min_bits = 0xFFFFFFFFu;
            g_max_bits = 0x00000000u;
            g_done     = 0u;
        }
        __syncthreads();   // smem union: hist view done, switch to otsu view

        sh.o.c[t] = ct;
        float hc = __fmul_rn(hv, ct);
        sh.o.w1[t] = hv; sh.o.s1[t] = hc;
        sh.o.w2[t] = hv; sh.o.s2[t] = hc;
        __syncthreads();

        #pragma unroll
        for (int s = 1; s < 256; s <<= 1) {
            float aw1 = (t >= s)      ? sh.o.w1[t - s] : 0.0f;
            float as1 = (t >= s)      ? sh.o.s1[t - s] : 0.0f;
            float aw2 = (t + s < 256) ? sh.o.w2[t + s] : 0.0f;
            float as2 = (t + s < 256) ? sh.o.s2[t + s] : 0.0f;
            __syncthreads();
            sh.o.w1[t] = __fadd_rn(sh.o.w1[t], aw1);
            sh.o.s1[t] = __fadd_rn(sh.o.s1[t], as1);
            sh.o.w2[t] = __fadd_rn(sh.o.w2[t], aw2);
            sh.o.s2[t] = __fadd_rn(sh.o.s2[t], as2);
            __syncthreads();
        }

        float v = -CUDART_INF_F;
        if (t < 255) {
            float m1 = sh.o.s1[t] / fmaxf(sh.o.w1[t], 1.0f);
            float m2 = sh.o.s2[t + 1] / fmaxf(sh.o.w2[t + 1], 1.0f);
            float d = __fadd_rn(m1, -m2);
            v = __fmul_rn(__fmul_rn(sh.o.w1[t], sh.o.w2[t + 1]), __fmul_rn(d, d));
        }
        sh.o.bv[t] = v; sh.o.bi[t] = t;
        __syncthreads();
        for (int s = 128; s; s >>= 1) {
            if (t < s) {
                float ov = sh.o.bv[t + s]; int oi = sh.o.bi[t + s];
                if (ov > sh.o.bv[t] || (ov == sh.o.bv[t] && oi < sh.o.bi[t])) {
                    sh.o.bv[t] = ov; sh.o.bi[t] = oi;
                }
            }
            __syncthreads();
        }
        if (t == 0) g_thresh = sh.o.c[sh.o.bi[0]];
    }
}

// ---------------- K3: direct binarize + tile (4x ILP, no prologue) ---------
__global__ void binarize_kernel(float* __restrict__ out, int npix) {
    const float thr = g_thresh;
    const int nout4 = (npix * 3) >> 2;
    const int stride = gridDim.x * blockDim.x;
    const float* __restrict__ gray = g_gray;
    float4* __restrict__ o4 = (float4*)out;
    const int t = threadIdx.x;

    int f = blockIdx.x * blockDim.x + t;
    for (; f + 3 * stride < nout4; f += 4 * stride) {
        #pragma unroll
        for (int u = 0; u < 4; u++) {
            const int fu = f + u * stride;
            const int e0 = 4 * fu;
            const int p0 = e0 / 3;
            const int r  = e0 - 3 * p0;
            float ga = __ldg(&gray[p0]);
            float gb = __ldg(&gray[p0 + 1]);
            float ba = (ga > thr) ? 1.0f : 0.0f;
            float bb = (gb > thr) ? 1.0f : 0.0f;
            float4 v;
            v.x = ba;
            v.y = (r < 2) ? ba : bb;
            v.z = (r < 1) ? ba : bb;
            v.w = bb;
            o4[fu] = v;
        }
    }
    for (; f < nout4; f += stride) {
        const int e0 = 4 * f;
        const int p0 = e0 / 3;
        const int r  = e0 - 3 * p0;
        float ga = __ldg(&gray[p0]);
        float gb = __ldg(&gray[p0 + 1]);
        float ba = (ga > thr) ? 1.0f : 0.0f;
        float bb = (gb > thr) ? 1.0f : 0.0f;
        float4 v;
        v.x = ba;
        v.y = (r < 2) ? ba : bb;
        v.z = (r < 1) ? ba : bb;
        v.w = bb;
        o4[f] = v;
    }
    for (int e = (nout4 << 2) + blockIdx.x * blockDim.x + t; e < npix * 3; e += stride) {
        float g = __ldg(&gray[e / 3]);
        out[e] = (g > thr) ? 1.0f : 0.0f;
    }
}

// ---------------- launch ---------------------------------------------------
extern "C" void kernel_launch(void* const* d_in, const int* in_sizes, int n_in,
                              void* d_out, int out_size) {
    const float* in = (const float*)d_in[0];
    float* out = (float*)d_out;
    int npix = in_sizes[0] / 3;

    gray_minmax_kernel<<<GRID, TB>>>(in, npix);
    hist_kernel<<<GRID, TB>>>(npix);
    binarize_kernel<<<GRID, TB>>>(out, npix);
}